// round 15
// baseline (speedup 1.0000x reference)
#include <cuda_runtime.h>
#include <cuda_bf16.h>
#include <mma.h>
#include <math.h>

using namespace nvcuda;

#define SEQ     2048
#define EMBD    1024
#define STATE   1024
#define QIN     2048
#define QUERY   256
#define NKB     10000
#define NKB_PAD 10112
#define VALUE   512
#define LSTMIN  1536
#define DECIN   2560
#define NTOK    32000
#define NB      148
#define NT      512

// ---------------- device scratch ----------------
__device__ __align__(16) __nv_bfloat16 g_dec_bf[SEQ * DECIN];   // [emb | val | hx] bf16
__device__ __align__(16) __nv_bfloat16 g_emb_bf[SEQ * EMBD];
__device__ __align__(16) float g_A1[SEQ * QIN];
__device__ __align__(16) float g_Gx[SEQ * 4 * STATE];
__device__ __align__(16) __nv_bfloat16 g_Wq1h_bf[STATE * QIN];
__device__ __align__(16) __nv_bfloat16 g_Wq1xT_bf[QIN * STATE];
__device__ __align__(16) __nv_bfloat16 g_Wihx_bf[4 * STATE * EMBD];
__device__ __align__(16) __nv_bfloat16 g_kbk_bf[NKB_PAD * QUERY];
__device__ __align__(16) __nv_bfloat16 g_Wq2_bf[QIN * QUERY];
__device__ __align__(16) float g_K2f[(size_t)NKB_PAD * QIN];
__device__ __align__(16) char g_K2_i8[(size_t)NKB * QIN];
__device__ __align__(16) float g_K2rs[NKB];
__device__ __align__(16) float g_kbias[NKB];
__device__ __align__(16) __nv_bfloat16 g_kbv_bf[NKB * VALUE];
__device__ __align__(16) __nv_bfloat16 g_Wihv_bf[4 * STATE * VALUE];
__device__ __align__(16) __nv_bfloat16 g_Whh_bf[4 * STATE * STATE];
__device__ __align__(16) __nv_bfloat16 g_Wdec_bf[NTOK * DECIN];
__device__ __align__(16) float g_qpre[2][4][QIN];
__device__ __align__(16) float g_vbuf[2][4][VALUE];
__device__ __align__(16) float g_z2[2][8 * 32];
__device__ __align__(16) float g_hxA[STATE];
__device__ __align__(16) float g_hxB[STATE];
__device__ __align__(16) float g_cx[STATE];
__device__ unsigned long long g_leaf[8 * 16];
__device__ unsigned long long g_root;
__device__ volatile unsigned long long g_gen;

// ---------------- helpers ----------------
__device__ __forceinline__ float bdot(uint4 u, float4 a, float4 b) {
    float2 p; float s;
    p = __bfloat1622float2(*(const __nv_bfloat162*)&u.x); s  = p.x * a.x + p.y * a.y;
    p = __bfloat1622float2(*(const __nv_bfloat162*)&u.y); s += p.x * a.z + p.y * a.w;
    p = __bfloat1622float2(*(const __nv_bfloat162*)&u.z); s += p.x * b.x + p.y * b.y;
    p = __bfloat1622float2(*(const __nv_bfloat162*)&u.w); s += p.x * b.z + p.y * b.w;
    return s;
}
__device__ __forceinline__ float sigmoidf_(float x) { return 1.0f / (1.0f + expf(-x)); }
__device__ __forceinline__ float wred(float a) {
#pragma unroll
    for (int o = 16; o; o >>= 1) a += __shfl_xor_sync(0xffffffffu, a, o);
    return a;
}
__device__ __forceinline__ int wredi(int a) {
#pragma unroll
    for (int o = 16; o; o >>= 1) a += __shfl_xor_sync(0xffffffffu, a, o);
    return a;
}
__device__ __forceinline__ int pack8(float a, float b, float c, float d) {
    int v0 = __float2int_rn(a * 127.0f), v1 = __float2int_rn(b * 127.0f);
    int v2 = __float2int_rn(c * 127.0f), v3 = __float2int_rn(d * 127.0f);
    return (v0 & 255) | ((v1 & 255) << 8) | ((v2 & 255) << 16) | ((v3 & 255) << 24);
}
#define CP_ASYNC16(dst, src) \
    asm volatile("cp.async.cg.shared.global [%0], [%1], 16;" :: "r"(dst), "l"(src))
#define CP_COMMIT() asm volatile("cp.async.commit_group;")
#define CP_WAIT(N)  asm volatile("cp.async.wait_group %0;" :: "n"(N))

// split tree barrier; release fence at arrive, NO acquire fence at wait.
__device__ __forceinline__ void grid_arrive(unsigned long long tgt, int b) {
    __syncthreads();
    if (threadIdx.x == 0) {
        __threadfence();
        const int grp = b & 7;
        const unsigned long long cnt = 18ull + ((grp < 4) ? 1ull : 0ull);
        if (atomicAdd(&g_leaf[grp * 16], 1ull) + 1ull == cnt * tgt)
            if (atomicAdd(&g_root, 1ull) + 1ull == 8ull * tgt) {
                __threadfence();
                g_gen = tgt;
            }
    }
}
__device__ __forceinline__ void grid_wait(unsigned long long &tgt) {
    if (threadIdx.x == 0) {
        while (g_gen < tgt) { }
    }
    __syncthreads();
    tgt++;
}

// ---------------- launch 0: fused prep ----------------
#define N4_KBV   (NKB * VALUE / 4)
#define N4_WHH   (4 * STATE * STATE / 4)
#define N4_WDEC  (NTOK * DECIN / 4)
#define N4_WIHV  (4 * STATE * VALUE / 4)
#define N4_WQ1H  (STATE * QIN / 4)
#define N4_WIHX  (4 * STATE * EMBD / 4)
#define N4_KBKB  (NKB * QUERY / 4)
#define N4_WQ2B  (QIN * QUERY / 4)
#define N4_TOT   (N4_KBV + N4_WHH + N4_WDEC + N4_WIHV + N4_WQ1H + N4_WIHX + N4_KBKB + N4_WQ2B)
#define NC_BLK   ((N4_TOT + 255) / 256)
#define TR_BLK   2048
#define KB_BLK   (NKB / 8)

__device__ __forceinline__ void conv4(const float* __restrict__ s, __nv_bfloat16* d, long i) {
    float4 v = ((const float4*)s)[i];
    ((__nv_bfloat162*)d)[i * 2]     = __floats2bfloat162_rn(v.x, v.y);
    ((__nv_bfloat162*)d)[i * 2 + 1] = __floats2bfloat162_rn(v.z, v.w);
}

__global__ void prep_kernel(const int* __restrict__ ids, const float* __restrict__ encW,
                            const float* __restrict__ kbk, const float* __restrict__ kbv,
                            const float* __restrict__ Whh, const float* __restrict__ Wdec,
                            const float* __restrict__ Wih, const float* __restrict__ Wq1,
                            const float* __restrict__ Wq2, const float* __restrict__ bq2) {
    __shared__ float tile[32][33];
    long bid = blockIdx.x;
    if (bid < NC_BLK) {
        long i = bid * 256 + threadIdx.x;
        if (i < N4_KBV) { conv4(kbv, g_kbv_bf, i); return; }
        i -= N4_KBV;
        if (i < N4_WHH) { conv4(Whh, g_Whh_bf, i); return; }
        i -= N4_WHH;
        if (i < N4_WDEC) { conv4(Wdec, g_Wdec_bf, i); return; }
        i -= N4_WDEC;
        if (i < N4_WIHV) {
            long row = i >> 7, col = (i & 127);
            float4 v = *(const float4*)(Wih + row * LSTMIN + EMBD + col * 4);
            ((__nv_bfloat162*)g_Wihv_bf)[i * 2]     = __floats2bfloat162_rn(v.x, v.y);
            ((__nv_bfloat162*)g_Wihv_bf)[i * 2 + 1] = __floats2bfloat162_rn(v.z, v.w);
            return;
        }
        i -= N4_WIHV;
        if (i < N4_WQ1H) { conv4(Wq1, g_Wq1h_bf, i); return; }
        i -= N4_WQ1H;
        if (i < N4_WIHX) {
            long row = i >> 8, col = (i & 255);
            float4 v = *(const float4*)(Wih + row * LSTMIN + col * 4);
            ((__nv_bfloat162*)g_Wihx_bf)[i * 2]     = __floats2bfloat162_rn(v.x, v.y);
            ((__nv_bfloat162*)g_Wihx_bf)[i * 2 + 1] = __floats2bfloat162_rn(v.z, v.w);
            return;
        }
        i -= N4_WIHX;
        if (i < N4_KBKB) { conv4(kbk, g_kbk_bf, i); return; }
        i -= N4_KBKB;
        if (i < N4_WQ2B) conv4(Wq2, g_Wq2_bf, i);
        return;
    }
    bid -= NC_BLK;
    if (bid < SEQ) {
        int t = (int)bid;
        int id = ids[t];
        for (int e = threadIdx.x; e < EMBD; e += 256) {
            __nv_bfloat16 v = __float2bfloat16(encW[(size_t)id * EMBD + e]);
            g_dec_bf[(size_t)t * DECIN + e] = v;
            g_emb_bf[(size_t)t * EMBD + e] = v;
        }
        if (t == 0) {
            for (int i = threadIdx.x; i < STATE; i += 256) {
                g_hxA[i] = 0.0f; g_hxB[i] = 0.0f; g_cx[i] = 0.0f;
            }
            for (int i = threadIdx.x; i < 2 * 4 * QIN; i += 256)
                ((float*)g_qpre)[i] = 0.0f;
            for (int i = threadIdx.x; i < 2 * 4 * VALUE; i += 256)
                ((float*)g_vbuf)[i] = 0.0f;
            for (int i = threadIdx.x; i < 2 * 8 * 32; i += 256)
                ((float*)g_z2)[i] = 0.0f;
        }
        return;
    }
    bid -= SEQ;
    if (bid < TR_BLK) {
        int bx = (int)(bid & 63), by = (int)(bid >> 6);
        int tx = threadIdx.x & 31, ty = threadIdx.x >> 5;
        int j0 = bx * 32, k0 = by * 32;
#pragma unroll
        for (int jj = 0; jj < 32; jj += 8)
            tile[ty + jj][tx] = Wq1[(size_t)(STATE + k0 + ty + jj) * QIN + j0 + tx];
        __syncthreads();
#pragma unroll
        for (int jj = 0; jj < 32; jj += 8)
            g_Wq1xT_bf[(size_t)(j0 + ty + jj) * STATE + k0 + tx] =
                __float2bfloat16(tile[tx][ty + jj]);
        return;
    }
    bid -= TR_BLK;
    int warp = threadIdx.x >> 5, lane = threadIdx.x & 31;
    int r = (int)bid * 8 + warp;
    if (r < NKB) {
        const float4* kr = (const float4*)(kbk + (size_t)r * QUERY);
        const float4* b4 = (const float4*)bq2;
        float a = 0.0f;
#pragma unroll
        for (int i = 0; i < 2; i++) {
            int c = lane + 32 * i;
            float4 k = kr[c], bb = b4[c];
            a += k.x * bb.x + k.y * bb.y + k.z * bb.z + k.w * bb.w;
        }
        a = wred(a);
        if (lane == 0) g_kbias[r] = a;
    }
}

// ------- single-sync cp.async K=64-stage bf16 wmma GEMM: C = A[MxK] @ B[NxK]^T -------
// dynamic smem: As[2][128][72] + Bs[2][128][72] bf16 = 73728 bytes
#define GEMM_SMEM (4 * 128 * 72 * 2)
__global__ __launch_bounds__(256) void wmma_gemm_kernel(
    const __nv_bfloat16* __restrict__ A, const __nv_bfloat16* __restrict__ B,
    float* __restrict__ C, int K, int ldc) {
    extern __shared__ __align__(16) __nv_bfloat16 gsm[];
    __nv_bfloat16 (*As)[128][72] = (__nv_bfloat16(*)[128][72])gsm;
    __nv_bfloat16 (*Bs)[128][72] = (__nv_bfloat16(*)[128][72])(gsm + 2 * 128 * 72);
    const int m0 = blockIdx.y * 128, n0 = blockIdx.x * 128;
    const int tid = threadIdx.x;
    const int warp = tid >> 5;
    const int wm = warp >> 2, wn = warp & 3;   // warp tile 64 x 32
    const int lr = tid >> 2;                   // 0..63
    const int lc = (tid & 3) * 16;             // 0,16,32,48

    // shared addresses for this thread's 8 cp.async targets (stage 0)
    unsigned a00 = (unsigned)__cvta_generic_to_shared(&As[0][lr][lc]);
    unsigned a01 = (unsigned)__cvta_generic_to_shared(&As[0][lr][lc + 8]);
    unsigned a10 = (unsigned)__cvta_generic_to_shared(&As[0][lr + 64][lc]);
    unsigned a11 = (unsigned)__cvta_generic_to_shared(&As[0][lr + 64][lc + 8]);
    unsigned b00 = (unsigned)__cvta_generic_to_shared(&Bs[0][lr][lc]);
    unsigned b01 = (unsigned)__cvta_generic_to_shared(&Bs[0][lr][lc + 8]);
    unsigned b10 = (unsigned)__cvta_generic_to_shared(&Bs[0][lr + 64][lc]);
    unsigned b11 = (unsigned)__cvta_generic_to_shared(&Bs[0][lr + 64][lc + 8]);
    const unsigned stg = (unsigned)(128 * 72 * 2);   // bytes per stage

    wmma::fragment<wmma::accumulator, 16, 16, 16, float> acc[4][2];
#pragma unroll
    for (int i = 0; i < 4; i++)
#pragma unroll
        for (int j = 0; j < 2; j++) wmma::fill_fragment(acc[i][j], 0.0f);

    const int KT = K >> 6;
    // prefetch stage 0 (tile 0)
    {
        CP_ASYNC16(a00, &A[(size_t)(m0 + lr) * K + lc]);
        CP_ASYNC16(a01, &A[(size_t)(m0 + lr) * K + lc + 8]);
        CP_ASYNC16(a10, &A[(size_t)(m0 + lr + 64) * K + lc]);
        CP_ASYNC16(a11, &A[(size_t)(m0 + lr + 64) * K + lc + 8]);
        CP_ASYNC16(b00, &B[(size_t)(n0 + lr) * K + lc]);
        CP_ASYNC16(b01, &B[(size_t)(n0 + lr) * K + lc + 8]);
        CP_ASYNC16(b10, &B[(size_t)(n0 + lr + 64) * K + lc]);
        CP_ASYNC16(b11, &B[(size_t)(n0 + lr + 64) * K + lc + 8]);
        CP_COMMIT();
    }
    for (int kt = 0; kt < KT; kt++) {
        const int st = kt & 1;
        // wait for tile kt (all groups), publish + protect via ONE sync, then issue kt+1
        CP_WAIT(0);
        __syncthreads();
        if (kt + 1 < KT) {
            const int k0 = (kt + 1) << 6;
            const unsigned o = (1 - st) * stg;
            CP_ASYNC16(a00 + o, &A[(size_t)(m0 + lr) * K + k0 + lc]);
            CP_ASYNC16(a01 + o, &A[(size_t)(m0 + lr) * K + k0 + lc + 8]);
            CP_ASYNC16(a10 + o, &A[(size_t)(m0 + lr + 64) * K + k0 + lc]);
            CP_ASYNC16(a11 + o, &A[(size_t)(m0 + lr + 64) * K + k0 + lc + 8]);
            CP_ASYNC16(b00 + o, &B[(size_t)(n0 + lr) * K + k0 + lc]);
            CP_ASYNC16(b01 + o, &B[(size_t)(n0 + lr) * K + k0 + lc + 8]);
            CP_ASYNC16(b10 + o, &B[(size_t)(n0 + lr + 64) * K + k0 + lc]);
            CP_ASYNC16(b11 + o, &B[(size_t)(n0 + lr + 64) * K + k0 + lc + 8]);
            CP_COMMIT();
        }
#pragma unroll
        for (int kk = 0; kk < 4; kk++) {
            wmma::fragment<wmma::matrix_a, 16, 16, 16, __nv_bfloat16, wmma::row_major> af[4];
            wmma::fragment<wmma::matrix_b, 16, 16, 16, __nv_bfloat16, wmma::col_major> bf[2];
#pragma unroll
            for (int i = 0; i < 4; i++)
                wmma::load_matrix_sync(af[i], &As[st][wm * 64 + i * 16][kk * 16], 72);
#pragma unroll
            for (int j = 0; j < 2; j++)
                wmma::load_matrix_sync(bf[j], &Bs[st][wn * 32 + j * 16][kk * 16], 72);
#pragma unroll
            for (int i = 0; i < 4; i++)
#pragma unroll
                for (int j = 0; j < 2; j++)
                    wmma::mma_sync(acc[i][j], af[i], bf[j], acc[i][j]);
        }
    }
#pragma unroll
    for (int i = 0; i < 4; i++)
#pragma unroll
        for (int j = 0; j < 2; j++)
            wmma::store_matrix_sync(&C[(size_t)(m0 + wm * 64 + i * 16) * ldc + n0 + wn * 32 + j * 16],
                                    acc[i][j], ldc, wmma::mem_row_major);
}

// ------- K2 fp32 -> int8 per-row quant -------
__global__ __launch_bounds__(256) void k2quant_kernel() {
    __shared__ float red[8];
    const int r = blockIdx.x;
    const int tid = threadIdx.x;
    const float* row = g_K2f + (size_t)r * QIN;
    float v[8];
    {
        float4 va = ((const float4*)row)[tid * 2];
        float4 vb = ((const float4*)row)[tid * 2 + 1];
        v[0] = va.x; v[1] = va.y; v[2] = va.z; v[3] = va.w;
        v[4] = vb.x; v[5] = vb.y; v[6] = vb.z; v[7] = vb.w;
    }
    float mx = 0.0f;
#pragma unroll
    for (int j = 0; j < 8; j++) mx = fmaxf(mx, fabsf(v[j]));
#pragma unroll
    for (int o = 16; o; o >>= 1) mx = fmaxf(mx, __shfl_xor_sync(0xffffffffu, mx, o));
    if ((tid & 31) == 0) red[tid >> 5] = mx;
    __syncthreads();
    float am = red[0];
#pragma unroll
    for (int i = 1; i < 8; i++) am = fmaxf(am, red[i]);
    float sc = (am > 0.0f) ? (127.0f / am) : 0.0f;
    uint2 o2;
    int b0 = __float2int_rn(v[0] * sc), b1 = __float2int_rn(v[1] * sc);
    int b2 = __float2int_rn(v[2] * sc), b3 = __float2int_rn(v[3] * sc);
    int b4 = __float2int_rn(v[4] * sc), b5 = __float2int_rn(v[5] * sc);
    int b6 = __float2int_rn(v[6] * sc), b7 = __float2int_rn(v[7] * sc);
    o2.x = (b0 & 255) | ((b1 & 255) << 8) | ((b2 & 255) << 16) | ((b3 & 255) << 24);
    o2.y = (b4 & 255) | ((b5 & 255) << 8) | ((b6 & 255) << 16) | ((b7 & 255) << 24);
    ((uint2*)(g_K2_i8 + (size_t)r * QIN))[tid] = o2;
    if (tid == 0) g_K2rs[r] = am / (127.0f * 127.0f);
}

// ---------------- persistent recurrent kernel: 2 barriers/step, warm L1 ----------------
#define OFF_PV4  0
#define OFF_E    8192
#define OFF_VAL  8480
#define OFF_GO   10528
#define OFF_HXN  10592
#define OFF_RS   10624
#define OFF_KB   10912
#define OFF_QH8  11200
#define OFF_HX   13248
#define OFF_KBV  17344
#define OFF_K2   86976
#define SMEM_REC 226240

__global__ __launch_bounds__(NT, 1) void recurrent_kernel(
    const float* __restrict__ bq1, const float* __restrict__ bih,
    const float* __restrict__ bhh) {
    extern __shared__ __align__(16) char dsm[];
    float4* s_pv4  = (float4*)(dsm + OFF_PV4);
    float*  s_e    = (float*)(dsm + OFF_E);
    float*  s_val  = (float*)(dsm + OFF_VAL);
    float*  s_go   = (float*)(dsm + OFF_GO);
    float*  s_hxn  = (float*)(dsm + OFF_HXN);
    float*  s_rs   = (float*)(dsm + OFF_RS);
    float*  s_kb   = (float*)(dsm + OFF_KB);
    unsigned* s_qh8 = (unsigned*)(dsm + OFF_QH8);
    float*  s_hx   = (float*)(dsm + OFF_HX);
    __nv_bfloat16* s_kbv = (__nv_bfloat16*)(dsm + OFF_KBV);
    char* s_K2 = dsm + OFF_K2;

    const int tid = threadIdx.x;
    const int warp = tid >> 5, lane = tid & 31;
    const int b = blockIdx.x;
    const int cp = b & 3;
    const int zc = (b & 7) * 32;
    const int r0 = (b * NKB) / NB;
    const int r1 = ((b + 1) * NKB) / NB;
    const int nl = r1 - r0;
    const int p = warp >> 1, half = warp & 1;
    const int s = b * 7 + p;
    const bool lst = (p < 7) && (s < STATE);
    const int j0 = half * 2048 + s, j1 = j0 + 1024;
    int nst = STATE - b * 7; nst = (nst < 0) ? 0 : ((nst > 7) ? 7 : nst);

    const float4 bq1r = ((const float4*)bq1)[tid];
    float bj0 = 0.0f, bj1 = 0.0f;
    if (lst && lane == 0) {
        bj0 = bih[j0] + bhh[j0];
        bj1 = bih[j1] + bhh[j1];
    }

    // ---- one-time smem fill ----
    {
        const uint4* src = (const uint4*)(g_kbv_bf + (size_t)r0 * VALUE);
        uint4* dst = (uint4*)s_kbv;
        for (int i = tid; i < nl * 64; i += NT) dst[i] = src[i];
        const uint4* k2s = (const uint4*)(g_K2_i8 + (size_t)r0 * QIN);
        uint4* k2d = (uint4*)s_K2;
        for (int i = tid; i < nl * 128; i += NT) k2d[i] = k2s[i];
        if (tid < nl) { s_rs[tid] = g_K2rs[r0 + tid]; s_kb[tid] = g_kbias[r0 + tid]; }
    }
    __syncthreads();

    unsigned long long tgt = g_gen + 1;
    float4 a1pre = ((const float4*)g_A1)[tid];

    for (int t = 0; t < SEQ; t++) {
        const int cur = t & 1, nxt = 1 - cur;
        const float* hxo = cur ? g_hxB : g_hxA;
        float* hxn = cur ? g_hxA : g_hxB;

        // ================= X: qh -> int8 scores -> val =================
        {
            float4 q0 = __ldcg((const float4*)g_qpre[cur][0] + tid);
            float4 q1 = __ldcg((const float4*)g_qpre[cur][1] + tid);
            float4 q2 = __ldcg((const float4*)g_qpre[cur][2] + tid);
            float4 q3 = __ldcg((const float4*)g_qpre[cur][3] + tid);
            float x0 = q0.x + q1.x + q2.x + q3.x + a1pre.x + bq1r.x;
            float x1 = q0.y + q1.y + q2.y + q3.y + a1pre.y + bq1r.y;
            float x2 = q0.z + q1.z + q2.z + q3.z + a1pre.z + bq1r.z;
            float x3 = q0.w + q1.w + q2.w + q3.w + a1pre.w + bq1r.w;
            s_qh8[tid] = pack8(tanhf(x0), tanhf(x1), tanhf(x2), tanhf(x3));
        }
        if (b == 147) {
            ((float4*)g_vbuf[nxt][tid >> 7])[tid & 127] = make_float4(0.f, 0.f, 0.f, 0.f);
            if (tid < 8) g_z2[nxt][tid * 32] = 0.0f;
        }
        __syncthreads();
        {
            int qreg[16];
#pragma unroll
            for (int i = 0; i < 16; i++) qreg[i] = (int)s_qh8[lane + 32 * i];
            for (int i = warp; i < nl; i += 16) {
                const int* krow = (const int*)(s_K2 + (size_t)i * QIN);
                int acc = 0;
#pragma unroll
                for (int k = 0; k < 16; k++)
                    acc = __dp4a(krow[lane + 32 * k], qreg[k], acc);
                acc = wredi(acc);
                if (lane == 0) s_e[i] = expf(fmaf((float)acc, s_rs[i], s_kb[i]));
            }
        }
        __syncthreads();
        {
            const int sub = tid >> 7;
            const int c4 = tid & 127;
            float4 a = make_float4(0.f, 0.f, 0.f, 0.f);
            const uint2* kv2 = (const uint2*)s_kbv;
            for (int i = sub; i < nl; i += 4) {
                uint2 u = kv2[i * 128 + c4];
                float2 p0 = __bfloat1622float2(*(const __nv_bfloat162*)&u.x);
                float2 p1 = __bfloat1622float2(*(const __nv_bfloat162*)&u.y);
                float e = s_e[i];
                a.x += e * p0.x; a.y += e * p0.y; a.z += e * p1.x; a.w += e * p1.y;
            }
            s_pv4[tid] = a;
            if (warp == 0) {
                float z = 0.0f;
                for (int i = lane; i < nl; i += 32) z += s_e[i];
                z = wred(z);
                if (lane == 0) atomicAdd(&g_z2[cur][zc], z);
            }
        }
        __syncthreads();
        if (tid < 128) {
            float4 r = s_pv4[tid];
            float4 u1 = s_pv4[tid + 128], u2 = s_pv4[tid + 256], u3 = s_pv4[tid + 384];
            r.x += u1.x + u2.x + u3.x;
            r.y += u1.y + u2.y + u3.y;
            r.z += u1.z + u2.z + u3.z;
            r.w += u1.w + u2.w + u3.w;
            atomicAdd((float4*)(g_vbuf[cur][cp] + tid * 4), r);
        }
        grid_arrive(tgt, b);

        // ===== hidden window (bar1): Whh·hx (L1-warm) =====
        if (tid < 256) ((float4*)s_hx)[tid] = __ldcg((const float4*)hxo + tid);
        __syncthreads();
        float a0 = 0.0f, a1 = 0.0f, gx0 = 0.0f, gx1 = 0.0f;
        if (lst) {
            const float4* h4 = (const float4*)s_hx;
            const uint4* wh0 = (const uint4*)(g_Whh_bf + (size_t)j0 * STATE);
            const uint4* wh1 = (const uint4*)(g_Whh_bf + (size_t)j1 * STATE);
#pragma unroll
            for (int i = 0; i < 4; i++) {
                int c = lane + 32 * i;
                float4 ha = h4[c * 2], hb = h4[c * 2 + 1];
                a0 += bdot(wh0[i * 32 + lane], ha, hb);
                a1 += bdot(wh1[i * 32 + lane], ha, hb);
            }
            if (lane == 0) {
                gx0 = g_Gx[(size_t)t * 4096 + j0] + bj0;
                gx1 = g_Gx[(size_t)t * 4096 + j1] + bj1;
            }
        }
        if (b == 147) {
            for (int i = tid; i < STATE; i += NT)
                g_dec_bf[(size_t)t * DECIN + EMBD + VALUE + i] = __float2bfloat16(s_hx[i]);
        }
        grid_wait(tgt);

        // ================= Y: val-dependent part + LSTM + qh_pre(t+1) =================
        float zz = 0.0f;
#pragma unroll
        for (int i = 0; i < 8; i++) zz += __ldcg(&g_z2[cur][i * 32]);
        const float invZ = 1.0f / zz;
        s_val[tid] = (__ldcg(&g_vbuf[cur][0][tid]) + __ldcg(&g_vbuf[cur][1][tid]) +
                      __ldcg(&g_vbuf[cur][2][tid]) + __ldcg(&g_vbuf[cur][3][tid])) * invZ;
        __syncthreads();

        if (lst) {
            const float4* v4 = (const float4*)s_val;
            const uint4* wv0 = (const uint4*)(g_Wihv_bf + (size_t)j0 * VALUE);
            const uint4* wv1 = (const uint4*)(g_Wihv_bf + (size_t)j1 * VALUE);
#pragma unroll
            for (int i = 0; i < 2; i++) {
                int c = lane + 32 * i;
                float4 va = v4[c * 2], vb = v4[c * 2 + 1];
                a0 += bdot(wv0[c], va, vb);
                a1 += bdot(wv1[c], va, vb);
            }
            a0 = wred(a0); a1 = wred(a1);
            if (lane == 0) {
                a0 += gx0;
                a1 += gx1;
                if (half) { s_go[p * 2] = a0; s_go[p * 2 + 1] = a1; }
            }
        }
        if (b == 146 && tid >= 128) {
            for (int i = tid - 128; i < VALUE; i += 384)
                g_dec_bf[(size_t)t * DECIN + EMBD + i] = __float2bfloat16(s_val[i]);
        }
        __syncthreads();
        if (lst && half == 0 && lane == 0) {
            float gg = s_go[p * 2], oo = s_go[p * 2 + 1];
            float c_old = g_cx[s];
            float cn = sigmoidf_(a1) * c_old + sigmoidf_(a0) * tanhf(gg);
            float hn = sigmoidf_(oo) * tanhf(cn);
            g_cx[s] = cn;
            hxn[s] = hn;
            s_hxn[p] = hn;
        }
        __syncthreads();
        if (nst > 0) {
            float4 acc = make_float4(0.f, 0.f, 0.f, 0.f);
            const __nv_bfloat16* wbase = g_Wq1h_bf + (size_t)(b * 7) * QIN + tid * 4;
            for (int pp = 0; pp < nst; pp++) {
                uint2 u = *(const uint2*)(wbase + (size_t)pp * QIN);
                float2 w0 = __bfloat1622float2(*(const __nv_bfloat162*)&u.x);
                float2 w1 = __bfloat1622float2(*(const __nv_bfloat162*)&u.y);
                float h = s_hxn[pp];
                acc.x += w0.x * h; acc.y += w0.y * h; acc.z += w1.x * h; acc.w += w1.y * h;
            }
            atomicAdd((float4*)(g_qpre[nxt][cp] + tid * 4), acc);
        }
        if (tid < 14) {
            int idx = b * 14 + tid;
            if (idx < 2048) ((float4*)g_qpre[cur])[idx] = make_float4(0.f, 0.f, 0.f, 0.f);
        }
        grid_arrive(tgt, b);
        {
            int tn = (t + 1 < SEQ) ? t + 1 : t;
            a1pre = ((const float4*)(g_A1 + (size_t)tn * QIN))[tid];
        }
        grid_wait(tgt);
    }
}

// ---------------- row-wise log_softmax (folds in decoder bias) ----------------
__global__ __launch_bounds__(256) void logsoftmax_kernel(float* __restrict__ out,
                                                         const float* __restrict__ bias) {
    __shared__ float red[8];
    const int row = blockIdx.x;
    float* x = out + (size_t)row * NTOK;
    const int tid = threadIdx.x;

    float m = -1e30f;
    for (int i = tid; i < NTOK; i += 256) m = fmaxf(m, x[i] + bias[i]);
#pragma unroll
    for (int o = 16; o; o >>= 1) m = fmaxf(m, __shfl_xor_sync(0xffffffffu, m, o));
    if ((tid & 31) == 0) red[tid >> 5] = m;
    __syncthreads();
    float mm = red[0];
#pragma unroll
    for (int i = 1; i < 8; i++) mm = fmaxf(mm, red[i]);
    __syncthreads();

    float sum = 0.0f;
    for (int i = tid; i < NTOK; i += 256) sum += expf(x[i] + bias[i] - mm);
    sum = wred(sum);
    if ((tid & 31) == 0) red[tid >> 5] = sum;
    __syncthreads();
    float ss = 0.0f;
#pragma unroll
    for (int i = 0; i < 8; i++) ss += red[i];
    float lse = mm + logf(ss);

    for (int i = tid; i < NTOK; i += 256) x[i] = x[i] + bias[i] - lse;
}

// ---------------- launch ----------------
extern "C" void kernel_launch(void* const* d_in, const int* in_sizes, int n_in,
                              void* d_out, int out_size) {
    const int*   ids  = (const int*)d_in[0];
    const float* encW = (const float*)d_in[1];
    const float* Wq1  = (const float*)d_in[2];
    const float* bq1  = (const float*)d_in[3];
    const float* Wq2  = (const float*)d_in[4];
    const float* bq2  = (const float*)d_in[5];
    const float* kbk  = (const float*)d_in[6];
    const float* kbv  = (const float*)d_in[7];
    const float* Wih  = (const float*)d_in[8];
    const float* bih  = (const float*)d_in[9];
    const float* Whh  = (const float*)d_in[10];
    const float* bhh  = (const float*)d_in[11];
    const float* Wdec = (const float*)d_in[12];
    const float* bdec = (const float*)d_in[13];
    float* out = (float*)d_out;

    float *p_A1, *p_Gx, *p_K2f;
    __nv_bfloat16 *p_emb, *p_wq1xT, *p_wihx, *p_kbkb, *p_wq2b, *p_decbf, *p_wdecb;
    cudaGetSymbolAddress((void**)&p_A1,    g_A1);
    cudaGetSymbolAddress((void**)&p_Gx,    g_Gx);
    cudaGetSymbolAddress((void**)&p_K2f,   g_K2f);
    cudaGetSymbolAddress((void**)&p_emb,   g_emb_bf);
    cudaGetSymbolAddress((void**)&p_wq1xT, g_Wq1xT_bf);
    cudaGetSymbolAddress((void**)&p_wihx,  g_Wihx_bf);
    cudaGetSymbolAddress((void**)&p_kbkb,  g_kbk_bf);
    cudaGetSymbolAddress((void**)&p_wq2b,  g_Wq2_bf);
    cudaGetSymbolAddress((void**)&p_decbf, g_dec_bf);
    cudaGetSymbolAddress((void**)&p_wdecb, g_Wdec_bf);

    cudaFuncSetAttribute(recurrent_kernel,
                         cudaFuncAttributeMaxDynamicSharedMemorySize, SMEM_REC);
    cudaFuncSetAttribute(wmma_gemm_kernel,
                         cudaFuncAttributeMaxDynamicSharedMemorySize, GEMM_SMEM);

    prep_kernel<<<NC_BLK + SEQ + TR_BLK + KB_BLK, 256>>>(
        ids, encW, kbk, kbv, Whh, Wdec, Wih, Wq1, Wq2, bq2);
    wmma_gemm_kernel<<<dim3(QIN / 128, SEQ / 128), 256, GEMM_SMEM>>>(
        p_emb, p_wq1xT, p_A1, EMBD, QIN);
    wmma_gemm_kernel<<<dim3(4096 / 128, SEQ / 128), 256, GEMM_SMEM>>>(
        p_emb, p_wihx, p_Gx, EMBD, 4096);
    wmma_gemm_kernel<<<dim3(QIN / 128, NKB_PAD / 128), 256, GEMM_SMEM>>>(
        p_kbkb, p_wq2b, p_K2f, QUERY, QIN);
    k2quant_kernel<<<NKB, 256>>>();
    recurrent_kernel<<<NB, NT, SMEM_REC>>>(bq1, bih, bhh);
    wmma_gemm_kernel<<<dim3(NTOK / 128, SEQ / 128), 256, GEMM_SMEM>>>(
        p_decbf, p_wdecb, out, DECIN, NTOK);
    logsoftmax_kernel<<<SEQ, 256>>>(out, bdec);
}

// round 16
// speedup vs baseline: 1.0165x; 1.0165x over previous
#include <cuda_runtime.h>
#include <cuda_bf16.h>
#include <mma.h>
#include <math.h>

using namespace nvcuda;

#define SEQ     2048
#define EMBD    1024
#define STATE   1024
#define QIN     2048
#define QUERY   256
#define NKB     10000
#define NKB_PAD 10112
#define VALUE   512
#define LSTMIN  1536
#define DECIN   2560
#define NTOK    32000
#define NB      148
#define NT      512

// ---------------- device scratch ----------------
__device__ __align__(16) __nv_bfloat16 g_dec_bf[SEQ * DECIN];   // [emb | val | hx] bf16
__device__ __align__(16) __nv_bfloat16 g_emb_bf[SEQ * EMBD];
__device__ __align__(16) float g_A1[SEQ * QIN];
__device__ __align__(16) float g_Gx[SEQ * 4 * STATE];
__device__ __align__(16) __nv_bfloat16 g_Wq1h_bf[STATE * QIN];
__device__ __align__(16) __nv_bfloat16 g_Wq1xT_bf[QIN * STATE];
__device__ __align__(16) __nv_bfloat16 g_Wihx_bf[4 * STATE * EMBD];
__device__ __align__(16) __nv_bfloat16 g_kbk_bf[NKB_PAD * QUERY];
__device__ __align__(16) __nv_bfloat16 g_Wq2_bf[QIN * QUERY];
__device__ __align__(16) float g_K2f[(size_t)NKB_PAD * QIN];
__device__ __align__(16) char g_K2_i8[(size_t)NKB * QIN];
__device__ __align__(16) float g_K2rs[NKB];
__device__ __align__(16) float g_kbias[NKB];
__device__ __align__(16) __nv_bfloat16 g_kbv_bf[NKB * VALUE];
__device__ __align__(16) __nv_bfloat16 g_Wihv_bf[4 * STATE * VALUE];
__device__ __align__(16) __nv_bfloat16 g_Whh_bf[4 * STATE * STATE];
__device__ __align__(16) __nv_bfloat16 g_Wdec_bf[NTOK * DECIN];
__device__ __align__(16) float g_qpre[2][4][QIN];
__device__ __align__(16) float g_vbuf[2][4][VALUE];
__device__ __align__(16) float g_z2[2][8 * 32];
__device__ __align__(16) float g_hxA[STATE];
__device__ __align__(16) float g_hxB[STATE];
__device__ __align__(16) float g_cx[STATE];
__device__ unsigned long long g_leaf[8 * 16];
__device__ unsigned long long g_root;
__device__ volatile unsigned long long g_gen;

// ---------------- helpers ----------------
__device__ __forceinline__ float bdot(uint4 u, float4 a, float4 b) {
    float2 p; float s;
    p = __bfloat1622float2(*(const __nv_bfloat162*)&u.x); s  = p.x * a.x + p.y * a.y;
    p = __bfloat1622float2(*(const __nv_bfloat162*)&u.y); s += p.x * a.z + p.y * a.w;
    p = __bfloat1622float2(*(const __nv_bfloat162*)&u.z); s += p.x * b.x + p.y * b.y;
    p = __bfloat1622float2(*(const __nv_bfloat162*)&u.w); s += p.x * b.z + p.y * b.w;
    return s;
}
__device__ __forceinline__ float sigmoidf_(float x) { return 1.0f / (1.0f + expf(-x)); }
__device__ __forceinline__ float wred(float a) {
#pragma unroll
    for (int o = 16; o; o >>= 1) a += __shfl_xor_sync(0xffffffffu, a, o);
    return a;
}
__device__ __forceinline__ int wredi(int a) {
#pragma unroll
    for (int o = 16; o; o >>= 1) a += __shfl_xor_sync(0xffffffffu, a, o);
    return a;
}
__device__ __forceinline__ int pack8(float a, float b, float c, float d) {
    int v0 = __float2int_rn(a * 127.0f), v1 = __float2int_rn(b * 127.0f);
    int v2 = __float2int_rn(c * 127.0f), v3 = __float2int_rn(d * 127.0f);
    return (v0 & 255) | ((v1 & 255) << 8) | ((v2 & 255) << 16) | ((v3 & 255) << 24);
}
#define CP_ASYNC16(dst, src) \
    asm volatile("cp.async.cg.shared.global [%0], [%1], 16;" :: "r"(dst), "l"(src))
#define CP_COMMIT() asm volatile("cp.async.commit_group;")
#define CP_WAIT(N)  asm volatile("cp.async.wait_group %0;" :: "n"(N))

// split tree barrier; release fence at arrive, NO acquire fence at wait.
__device__ __forceinline__ void grid_arrive(unsigned long long tgt, int b) {
    __syncthreads();
    if (threadIdx.x == 0) {
        __threadfence();
        const int grp = b & 7;
        const unsigned long long cnt = 18ull + ((grp < 4) ? 1ull : 0ull);
        if (atomicAdd(&g_leaf[grp * 16], 1ull) + 1ull == cnt * tgt)
            if (atomicAdd(&g_root, 1ull) + 1ull == 8ull * tgt) {
                __threadfence();
                g_gen = tgt;
            }
    }
}
__device__ __forceinline__ void grid_wait(unsigned long long &tgt) {
    if (threadIdx.x == 0) {
        while (g_gen < tgt) { }
    }
    __syncthreads();
    tgt++;
}

// ---------------- launch 0: fused prep ----------------
#define N4_KBV   (NKB * VALUE / 4)
#define N4_WHH   (4 * STATE * STATE / 4)
#define N4_WDEC  (NTOK * DECIN / 4)
#define N4_WIHV  (4 * STATE * VALUE / 4)
#define N4_WQ1H  (STATE * QIN / 4)
#define N4_WIHX  (4 * STATE * EMBD / 4)
#define N4_KBKB  (NKB * QUERY / 4)
#define N4_WQ2B  (QIN * QUERY / 4)
#define N4_TOT   (N4_KBV + N4_WHH + N4_WDEC + N4_WIHV + N4_WQ1H + N4_WIHX + N4_KBKB + N4_WQ2B)
#define NC_BLK   ((N4_TOT + 255) / 256)
#define TR_BLK   2048
#define KB_BLK   (NKB / 8)

__device__ __forceinline__ void conv4(const float* __restrict__ s, __nv_bfloat16* d, long i) {
    float4 v = ((const float4*)s)[i];
    ((__nv_bfloat162*)d)[i * 2]     = __floats2bfloat162_rn(v.x, v.y);
    ((__nv_bfloat162*)d)[i * 2 + 1] = __floats2bfloat162_rn(v.z, v.w);
}

__global__ void prep_kernel(const int* __restrict__ ids, const float* __restrict__ encW,
                            const float* __restrict__ kbk, const float* __restrict__ kbv,
                            const float* __restrict__ Whh, const float* __restrict__ Wdec,
                            const float* __restrict__ Wih, const float* __restrict__ Wq1,
                            const float* __restrict__ Wq2, const float* __restrict__ bq2) {
    __shared__ float tile[32][33];
    long bid = blockIdx.x;
    if (bid < NC_BLK) {
        long i = bid * 256 + threadIdx.x;
        if (i < N4_KBV) { conv4(kbv, g_kbv_bf, i); return; }
        i -= N4_KBV;
        if (i < N4_WHH) { conv4(Whh, g_Whh_bf, i); return; }
        i -= N4_WHH;
        if (i < N4_WDEC) { conv4(Wdec, g_Wdec_bf, i); return; }
        i -= N4_WDEC;
        if (i < N4_WIHV) {
            long row = i >> 7, col = (i & 127);
            float4 v = *(const float4*)(Wih + row * LSTMIN + EMBD + col * 4);
            ((__nv_bfloat162*)g_Wihv_bf)[i * 2]     = __floats2bfloat162_rn(v.x, v.y);
            ((__nv_bfloat162*)g_Wihv_bf)[i * 2 + 1] = __floats2bfloat162_rn(v.z, v.w);
            return;
        }
        i -= N4_WIHV;
        if (i < N4_WQ1H) { conv4(Wq1, g_Wq1h_bf, i); return; }
        i -= N4_WQ1H;
        if (i < N4_WIHX) {
            long row = i >> 8, col = (i & 255);
            float4 v = *(const float4*)(Wih + row * LSTMIN + col * 4);
            ((__nv_bfloat162*)g_Wihx_bf)[i * 2]     = __floats2bfloat162_rn(v.x, v.y);
            ((__nv_bfloat162*)g_Wihx_bf)[i * 2 + 1] = __floats2bfloat162_rn(v.z, v.w);
            return;
        }
        i -= N4_WIHX;
        if (i < N4_KBKB) { conv4(kbk, g_kbk_bf, i); return; }
        i -= N4_KBKB;
        if (i < N4_WQ2B) conv4(Wq2, g_Wq2_bf, i);
        return;
    }
    bid -= NC_BLK;
    if (bid < SEQ) {
        int t = (int)bid;
        int id = ids[t];
        for (int e = threadIdx.x; e < EMBD; e += 256) {
            __nv_bfloat16 v = __float2bfloat16(encW[(size_t)id * EMBD + e]);
            g_dec_bf[(size_t)t * DECIN + e] = v;
            g_emb_bf[(size_t)t * EMBD + e] = v;
        }
        if (t == 0) {
            for (int i = threadIdx.x; i < STATE; i += 256) {
                g_hxA[i] = 0.0f; g_hxB[i] = 0.0f; g_cx[i] = 0.0f;
            }
            for (int i = threadIdx.x; i < 2 * 4 * QIN; i += 256)
                ((float*)g_qpre)[i] = 0.0f;
            for (int i = threadIdx.x; i < 2 * 4 * VALUE; i += 256)
                ((float*)g_vbuf)[i] = 0.0f;
            for (int i = threadIdx.x; i < 2 * 8 * 32; i += 256)
                ((float*)g_z2)[i] = 0.0f;
        }
        return;
    }
    bid -= SEQ;
    if (bid < TR_BLK) {
        int bx = (int)(bid & 63), by = (int)(bid >> 6);
        int tx = threadIdx.x & 31, ty = threadIdx.x >> 5;
        int j0 = bx * 32, k0 = by * 32;
#pragma unroll
        for (int jj = 0; jj < 32; jj += 8)
            tile[ty + jj][tx] = Wq1[(size_t)(STATE + k0 + ty + jj) * QIN + j0 + tx];
        __syncthreads();
#pragma unroll
        for (int jj = 0; jj < 32; jj += 8)
            g_Wq1xT_bf[(size_t)(j0 + ty + jj) * STATE + k0 + tx] =
                __float2bfloat16(tile[tx][ty + jj]);
        return;
    }
    bid -= TR_BLK;
    int warp = threadIdx.x >> 5, lane = threadIdx.x & 31;
    int r = (int)bid * 8 + warp;
    if (r < NKB) {
        const float4* kr = (const float4*)(kbk + (size_t)r * QUERY);
        const float4* b4 = (const float4*)bq2;
        float a = 0.0f;
#pragma unroll
        for (int i = 0; i < 2; i++) {
            int c = lane + 32 * i;
            float4 k = kr[c], bb = b4[c];
            a += k.x * bb.x + k.y * bb.y + k.z * bb.z + k.w * bb.w;
        }
        a = wred(a);
        if (lane == 0) g_kbias[r] = a;
    }
}

// ------- R14-proven cp.async double-buffered bf16 wmma GEMM: C = A[MxK] @ B[NxK]^T -------
__global__ __launch_bounds__(256) void wmma_gemm_kernel(
    const __nv_bfloat16* __restrict__ A, const __nv_bfloat16* __restrict__ B,
    float* __restrict__ C, int K, int ldc) {
    __shared__ __nv_bfloat16 As[2][128][40];
    __shared__ __nv_bfloat16 Bs[2][128][40];
    const int m0 = blockIdx.y * 128, n0 = blockIdx.x * 128;
    const int tid = threadIdx.x;
    const int warp = tid >> 5;
    const int wm = warp >> 2, wn = warp & 3;
    const int lr = tid >> 2;
    const int lc = (tid & 3) * 8;

    unsigned sa0 = (unsigned)__cvta_generic_to_shared(&As[0][lr][lc]);
    unsigned sa1 = (unsigned)__cvta_generic_to_shared(&As[0][lr + 64][lc]);
    unsigned sb0 = (unsigned)__cvta_generic_to_shared(&Bs[0][lr][lc]);
    unsigned sb1 = (unsigned)__cvta_generic_to_shared(&Bs[0][lr + 64][lc]);
    const unsigned stg = (unsigned)(128 * 40 * 2);

    wmma::fragment<wmma::accumulator, 16, 16, 16, float> acc[4][2];
#pragma unroll
    for (int i = 0; i < 4; i++)
#pragma unroll
        for (int j = 0; j < 2; j++) wmma::fill_fragment(acc[i][j], 0.0f);

    const int KT = K >> 5;
    {
        CP_ASYNC16(sa0, &A[(size_t)(m0 + lr) * K + lc]);
        CP_ASYNC16(sa1, &A[(size_t)(m0 + lr + 64) * K + lc]);
        CP_ASYNC16(sb0, &B[(size_t)(n0 + lr) * K + lc]);
        CP_ASYNC16(sb1, &B[(size_t)(n0 + lr + 64) * K + lc]);
        CP_COMMIT();
    }
    for (int kt = 0; kt < KT; kt++) {
        const int st = kt & 1;
        if (kt + 1 < KT) {
            const int k0 = (kt + 1) << 5;
            const unsigned o = (1 - st) * stg;
            CP_ASYNC16(sa0 + o, &A[(size_t)(m0 + lr) * K + k0 + lc]);
            CP_ASYNC16(sa1 + o, &A[(size_t)(m0 + lr + 64) * K + k0 + lc]);
            CP_ASYNC16(sb0 + o, &B[(size_t)(n0 + lr) * K + k0 + lc]);
            CP_ASYNC16(sb1 + o, &B[(size_t)(n0 + lr + 64) * K + k0 + lc]);
            CP_COMMIT();
            CP_WAIT(1);
        } else {
            CP_WAIT(0);
        }
        __syncthreads();
#pragma unroll
        for (int kk = 0; kk < 2; kk++) {
            wmma::fragment<wmma::matrix_a, 16, 16, 16, __nv_bfloat16, wmma::row_major> af[4];
            wmma::fragment<wmma::matrix_b, 16, 16, 16, __nv_bfloat16, wmma::col_major> bf[2];
#pragma unroll
            for (int i = 0; i < 4; i++)
                wmma::load_matrix_sync(af[i], &As[st][wm * 64 + i * 16][kk * 16], 40);
#pragma unroll
            for (int j = 0; j < 2; j++)
                wmma::load_matrix_sync(bf[j], &Bs[st][wn * 32 + j * 16][kk * 16], 40);
#pragma unroll
            for (int i = 0; i < 4; i++)
#pragma unroll
                for (int j = 0; j < 2; j++)
                    wmma::mma_sync(acc[i][j], af[i], bf[j], acc[i][j]);
        }
        __syncthreads();
    }
#pragma unroll
    for (int i = 0; i < 4; i++)
#pragma unroll
        for (int j = 0; j < 2; j++)
            wmma::store_matrix_sync(&C[(size_t)(m0 + wm * 64 + i * 16) * ldc + n0 + wn * 32 + j * 16],
                                    acc[i][j], ldc, wmma::mem_row_major);
}

// ------- K2 fp32 -> int8 per-row quant -------
__global__ __launch_bounds__(256) void k2quant_kernel() {
    __shared__ float red[8];
    const int r = blockIdx.x;
    const int tid = threadIdx.x;
    const float* row = g_K2f + (size_t)r * QIN;
    float v[8];
    {
        float4 va = ((const float4*)row)[tid * 2];
        float4 vb = ((const float4*)row)[tid * 2 + 1];
        v[0] = va.x; v[1] = va.y; v[2] = va.z; v[3] = va.w;
        v[4] = vb.x; v[5] = vb.y; v[6] = vb.z; v[7] = vb.w;
    }
    float mx = 0.0f;
#pragma unroll
    for (int j = 0; j < 8; j++) mx = fmaxf(mx, fabsf(v[j]));
#pragma unroll
    for (int o = 16; o; o >>= 1) mx = fmaxf(mx, __shfl_xor_sync(0xffffffffu, mx, o));
    if ((tid & 31) == 0) red[tid >> 5] = mx;
    __syncthreads();
    float am = red[0];
#pragma unroll
    for (int i = 1; i < 8; i++) am = fmaxf(am, red[i]);
    float sc = (am > 0.0f) ? (127.0f / am) : 0.0f;
    uint2 o2;
    int b0 = __float2int_rn(v[0] * sc), b1 = __float2int_rn(v[1] * sc);
    int b2 = __float2int_rn(v[2] * sc), b3 = __float2int_rn(v[3] * sc);
    int b4 = __float2int_rn(v[4] * sc), b5 = __float2int_rn(v[5] * sc);
    int b6 = __float2int_rn(v[6] * sc), b7 = __float2int_rn(v[7] * sc);
    o2.x = (b0 & 255) | ((b1 & 255) << 8) | ((b2 & 255) << 16) | ((b3 & 255) << 24);
    o2.y = (b4 & 255) | ((b5 & 255) << 8) | ((b6 & 255) << 16) | ((b7 & 255) << 24);
    ((uint2*)(g_K2_i8 + (size_t)r * QIN))[tid] = o2;
    if (tid == 0) g_K2rs[r] = am / (127.0f * 127.0f);
}

// ---------------- persistent recurrent kernel: 2 barriers/step, warm L1 ----------------
#define OFF_PV4  0
#define OFF_E    8192
#define OFF_VAL  8480
#define OFF_GO   10528
#define OFF_HXN  10592
#define OFF_RS   10624
#define OFF_KB   10912
#define OFF_QH8  11200
#define OFF_HX   13248
#define OFF_KBV  17344
#define OFF_K2   86976
#define SMEM_REC 226240

__global__ __launch_bounds__(NT, 1) void recurrent_kernel(
    const float* __restrict__ bq1, const float* __restrict__ bih,
    const float* __restrict__ bhh) {
    extern __shared__ __align__(16) char dsm[];
    float4* s_pv4  = (float4*)(dsm + OFF_PV4);
    float*  s_e    = (float*)(dsm + OFF_E);
    float*  s_val  = (float*)(dsm + OFF_VAL);
    float*  s_go   = (float*)(dsm + OFF_GO);
    float*  s_hxn  = (float*)(dsm + OFF_HXN);
    float*  s_rs   = (float*)(dsm + OFF_RS);
    float*  s_kb   = (float*)(dsm + OFF_KB);
    unsigned* s_qh8 = (unsigned*)(dsm + OFF_QH8);
    float*  s_hx   = (float*)(dsm + OFF_HX);
    __nv_bfloat16* s_kbv = (__nv_bfloat16*)(dsm + OFF_KBV);
    char* s_K2 = dsm + OFF_K2;

    const int tid = threadIdx.x;
    const int warp = tid >> 5, lane = tid & 31;
    const int b = blockIdx.x;
    const int cp = b & 3;
    const int zc = (b & 7) * 32;
    const int r0 = (b * NKB) / NB;
    const int r1 = ((b + 1) * NKB) / NB;
    const int nl = r1 - r0;
    const int p = warp >> 1, half = warp & 1;
    const int s = b * 7 + p;
    const bool lst = (p < 7) && (s < STATE);
    const int j0 = half * 2048 + s, j1 = j0 + 1024;
    int nst = STATE - b * 7; nst = (nst < 0) ? 0 : ((nst > 7) ? 7 : nst);

    const float4 bq1r = ((const float4*)bq1)[tid];
    float bj0 = 0.0f, bj1 = 0.0f;
    if (lst && lane == 0) {
        bj0 = bih[j0] + bhh[j0];
        bj1 = bih[j1] + bhh[j1];
    }

    // ---- one-time smem fill ----
    {
        const uint4* src = (const uint4*)(g_kbv_bf + (size_t)r0 * VALUE);
        uint4* dst = (uint4*)s_kbv;
        for (int i = tid; i < nl * 64; i += NT) dst[i] = src[i];
        const uint4* k2s = (const uint4*)(g_K2_i8 + (size_t)r0 * QIN);
        uint4* k2d = (uint4*)s_K2;
        for (int i = tid; i < nl * 128; i += NT) k2d[i] = k2s[i];
        if (tid < nl) { s_rs[tid] = g_K2rs[r0 + tid]; s_kb[tid] = g_kbias[r0 + tid]; }
    }
    __syncthreads();

    unsigned long long tgt = g_gen + 1;
    float4 a1pre = ((const float4*)g_A1)[tid];

    for (int t = 0; t < SEQ; t++) {
        const int cur = t & 1, nxt = 1 - cur;
        const float* hxo = cur ? g_hxB : g_hxA;
        float* hxn = cur ? g_hxA : g_hxB;

        // ================= X: qh -> int8 scores -> val =================
        {
            float4 q0 = __ldcg((const float4*)g_qpre[cur][0] + tid);
            float4 q1 = __ldcg((const float4*)g_qpre[cur][1] + tid);
            float4 q2 = __ldcg((const float4*)g_qpre[cur][2] + tid);
            float4 q3 = __ldcg((const float4*)g_qpre[cur][3] + tid);
            float x0 = q0.x + q1.x + q2.x + q3.x + a1pre.x + bq1r.x;
            float x1 = q0.y + q1.y + q2.y + q3.y + a1pre.y + bq1r.y;
            float x2 = q0.z + q1.z + q2.z + q3.z + a1pre.z + bq1r.z;
            float x3 = q0.w + q1.w + q2.w + q3.w + a1pre.w + bq1r.w;
            s_qh8[tid] = pack8(tanhf(x0), tanhf(x1), tanhf(x2), tanhf(x3));
        }
        if (b == 147) {
            ((float4*)g_vbuf[nxt][tid >> 7])[tid & 127] = make_float4(0.f, 0.f, 0.f, 0.f);
            if (tid < 8) g_z2[nxt][tid * 32] = 0.0f;
        }
        __syncthreads();
        {
            int qreg[16];
#pragma unroll
            for (int i = 0; i < 16; i++) qreg[i] = (int)s_qh8[lane + 32 * i];
            for (int i = warp; i < nl; i += 16) {
                const int* krow = (const int*)(s_K2 + (size_t)i * QIN);
                int acc = 0;
#pragma unroll
                for (int k = 0; k < 16; k++)
                    acc = __dp4a(krow[lane + 32 * k], qreg[k], acc);
                acc = wredi(acc);
                if (lane == 0) s_e[i] = expf(fmaf((float)acc, s_rs[i], s_kb[i]));
            }
        }
        __syncthreads();
        {
            const int sub = tid >> 7;
            const int c4 = tid & 127;
            float4 a = make_float4(0.f, 0.f, 0.f, 0.f);
            const uint2* kv2 = (const uint2*)s_kbv;
            for (int i = sub; i < nl; i += 4) {
                uint2 u = kv2[i * 128 + c4];
                float2 p0 = __bfloat1622float2(*(const __nv_bfloat162*)&u.x);
                float2 p1 = __bfloat1622float2(*(const __nv_bfloat162*)&u.y);
                float e = s_e[i];
                a.x += e * p0.x; a.y += e * p0.y; a.z += e * p1.x; a.w += e * p1.y;
            }
            s_pv4[tid] = a;
            if (warp == 0) {
                float z = 0.0f;
                for (int i = lane; i < nl; i += 32) z += s_e[i];
                z = wred(z);
                if (lane == 0) atomicAdd(&g_z2[cur][zc], z);
            }
        }
        __syncthreads();
        if (tid < 128) {
            float4 r = s_pv4[tid];
            float4 u1 = s_pv4[tid + 128], u2 = s_pv4[tid + 256], u3 = s_pv4[tid + 384];
            r.x += u1.x + u2.x + u3.x;
            r.y += u1.y + u2.y + u3.y;
            r.z += u1.z + u2.z + u3.z;
            r.w += u1.w + u2.w + u3.w;
            atomicAdd((float4*)(g_vbuf[cur][cp] + tid * 4), r);
        }
        grid_arrive(tgt, b);

        // ===== hidden window (bar1): Whh·hx (L1-warm) =====
        if (tid < 256) ((float4*)s_hx)[tid] = __ldcg((const float4*)hxo + tid);
        __syncthreads();
        float a0 = 0.0f, a1 = 0.0f, gx0 = 0.0f, gx1 = 0.0f;
        if (lst) {
            const float4* h4 = (const float4*)s_hx;
            const uint4* wh0 = (const uint4*)(g_Whh_bf + (size_t)j0 * STATE);
            const uint4* wh1 = (const uint4*)(g_Whh_bf + (size_t)j1 * STATE);
#pragma unroll
            for (int i = 0; i < 4; i++) {
                int c = lane + 32 * i;
                float4 ha = h4[c * 2], hb = h4[c * 2 + 1];
                a0 += bdot(wh0[i * 32 + lane], ha, hb);
                a1 += bdot(wh1[i * 32 + lane], ha, hb);
            }
            if (lane == 0) {
                gx0 = g_Gx[(size_t)t * 4096 + j0] + bj0;
                gx1 = g_Gx[(size_t)t * 4096 + j1] + bj1;
            }
        }
        if (b == 147) {
            for (int i = tid; i < STATE; i += NT)
                g_dec_bf[(size_t)t * DECIN + EMBD + VALUE + i] = __float2bfloat16(s_hx[i]);
        }
        grid_wait(tgt);

        // ================= Y: val-dependent part + LSTM + qh_pre(t+1) =================
        float zz = 0.0f;
#pragma unroll
        for (int i = 0; i < 8; i++) zz += __ldcg(&g_z2[cur][i * 32]);
        const float invZ = 1.0f / zz;
        s_val[tid] = (__ldcg(&g_vbuf[cur][0][tid]) + __ldcg(&g_vbuf[cur][1][tid]) +
                      __ldcg(&g_vbuf[cur][2][tid]) + __ldcg(&g_vbuf[cur][3][tid])) * invZ;
        __syncthreads();

        if (lst) {
            const float4* v4 = (const float4*)s_val;
            const uint4* wv0 = (const uint4*)(g_Wihv_bf + (size_t)j0 * VALUE);
            const uint4* wv1 = (const uint4*)(g_Wihv_bf + (size_t)j1 * VALUE);
#pragma unroll
            for (int i = 0; i < 2; i++) {
                int c = lane + 32 * i;
                float4 va = v4[c * 2], vb = v4[c * 2 + 1];
                a0 += bdot(wv0[c], va, vb);
                a1 += bdot(wv1[c], va, vb);
            }
            a0 = wred(a0); a1 = wred(a1);
            if (lane == 0) {
                a0 += gx0;
                a1 += gx1;
                if (half) { s_go[p * 2] = a0; s_go[p * 2 + 1] = a1; }
            }
        }
        if (b == 146 && tid >= 128) {
            for (int i = tid - 128; i < VALUE; i += 384)
                g_dec_bf[(size_t)t * DECIN + EMBD + i] = __float2bfloat16(s_val[i]);
        }
        __syncthreads();
        if (lst && half == 0 && lane == 0) {
            float gg = s_go[p * 2], oo = s_go[p * 2 + 1];
            float c_old = g_cx[s];
            float cn = sigmoidf_(a1) * c_old + sigmoidf_(a0) * tanhf(gg);
            float hn = sigmoidf_(oo) * tanhf(cn);
            g_cx[s] = cn;
            hxn[s] = hn;
            s_hxn[p] = hn;
        }
        __syncthreads();
        if (nst > 0) {
            float4 acc = make_float4(0.f, 0.f, 0.f, 0.f);
            const __nv_bfloat16* wbase = g_Wq1h_bf + (size_t)(b * 7) * QIN + tid * 4;
            for (int pp = 0; pp < nst; pp++) {
                uint2 u = *(const uint2*)(wbase + (size_t)pp * QIN);
                float2 w0 = __bfloat1622float2(*(const __nv_bfloat162*)&u.x);
                float2 w1 = __bfloat1622float2(*(const __nv_bfloat162*)&u.y);
                float h = s_hxn[pp];
                acc.x += w0.x * h; acc.y += w0.y * h; acc.z += w1.x * h; acc.w += w1.y * h;
            }
            atomicAdd((float4*)(g_qpre[nxt][cp] + tid * 4), acc);
        }
        if (tid < 14) {
            int idx = b * 14 + tid;
            if (idx < 2048) ((float4*)g_qpre[cur])[idx] = make_float4(0.f, 0.f, 0.f, 0.f);
        }
        grid_arrive(tgt, b);
        {
            int tn = (t + 1 < SEQ) ? t + 1 : t;
            a1pre = ((const float4*)(g_A1 + (size_t)tn * QIN))[tid];
        }
        grid_wait(tgt);
    }
}

// ---------------- online single-pass log_softmax (folds in decoder bias) ----------------
__global__ __launch_bounds__(512) void logsoftmax_kernel(float* __restrict__ out,
                                                         const float* __restrict__ bias) {
    __shared__ float redm[16], reds[16];
    const int row = blockIdx.x;
    float* x = out + (size_t)row * NTOK;
    const int tid = threadIdx.x;

    // online max/sum in ONE read pass
    float m = -1e30f, sum = 0.0f;
    for (int i = tid; i < NTOK; i += 512) {
        float v = x[i] + bias[i];
        if (v > m) { sum = sum * expf(m - v) + 1.0f; m = v; }
        else sum += expf(v - m);
    }
    // warp merge of (m, sum)
#pragma unroll
    for (int o = 16; o; o >>= 1) {
        float mo = __shfl_xor_sync(0xffffffffu, m, o);
        float so = __shfl_xor_sync(0xffffffffu, sum, o);
        float mn = fmaxf(m, mo);
        sum = sum * expf(m - mn) + so * expf(mo - mn);
        m = mn;
    }
    if ((tid & 31) == 0) { redm[tid >> 5] = m; reds[tid >> 5] = sum; }
    __syncthreads();
    // block merge (16 warps)
    float mm = redm[0], ss = reds[0];
#pragma unroll
    for (int i = 1; i < 16; i++) {
        float mo = redm[i], so = reds[i];
        float mn = fmaxf(mm, mo);
        ss = ss * expf(mm - mn) + so * expf(mo - mn);
        mm = mn;
    }
    float lse = mm + logf(ss);

    for (int i = tid; i < NTOK; i += 512) x[i] = x[i] + bias[i] - lse;
}

// ---------------- launch ----------------
extern "C" void kernel_launch(void* const* d_in, const int* in_sizes, int n_in,
                              void* d_out, int out_size) {
    const int*   ids  = (const int*)d_in[0];
    const float* encW = (const float*)d_in[1];
    const float* Wq1  = (const float*)d_in[2];
    const float* bq1  = (const float*)d_in[3];
    const float* Wq2  = (const float*)d_in[4];
    const float* bq2  = (const float*)d_in[5];
    const float* kbk  = (const float*)d_in[6];
    const float* kbv  = (const float*)d_in[7];
    const float* Wih  = (const float*)d_in[8];
    const float* bih  = (const float*)d_in[9];
    const float* Whh  = (const float*)d_in[10];
    const float* bhh  = (const float*)d_in[11];
    const float* Wdec = (const float*)d_in[12];
    const float* bdec = (const float*)d_in[13];
    float* out = (float*)d_out;

    float *p_A1, *p_Gx, *p_K2f;
    __nv_bfloat16 *p_emb, *p_wq1xT, *p_wihx, *p_kbkb, *p_wq2b, *p_decbf, *p_wdecb;
    cudaGetSymbolAddress((void**)&p_A1,    g_A1);
    cudaGetSymbolAddress((void**)&p_Gx,    g_Gx);
    cudaGetSymbolAddress((void**)&p_K2f,   g_K2f);
    cudaGetSymbolAddress((void**)&p_emb,   g_emb_bf);
    cudaGetSymbolAddress((void**)&p_wq1xT, g_Wq1xT_bf);
    cudaGetSymbolAddress((void**)&p_wihx,  g_Wihx_bf);
    cudaGetSymbolAddress((void**)&p_kbkb,  g_kbk_bf);
    cudaGetSymbolAddress((void**)&p_wq2b,  g_Wq2_bf);
    cudaGetSymbolAddress((void**)&p_decbf, g_dec_bf);
    cudaGetSymbolAddress((void**)&p_wdecb, g_Wdec_bf);

    cudaFuncSetAttribute(recurrent_kernel,
                         cudaFuncAttributeMaxDynamicSharedMemorySize, SMEM_REC);

    prep_kernel<<<NC_BLK + SEQ + TR_BLK + KB_BLK, 256>>>(
        ids, encW, kbk, kbv, Whh, Wdec, Wih, Wq1, Wq2, bq2);
    wmma_gemm_kernel<<<dim3(QIN / 128, SEQ / 128), 256>>>(p_emb, p_wq1xT, p_A1, EMBD, QIN);
    wmma_gemm_kernel<<<dim3(4096 / 128, SEQ / 128), 256>>>(p_emb, p_wihx, p_Gx, EMBD, 4096);
    wmma_gemm_kernel<<<dim3(QIN / 128, NKB_PAD / 128), 256>>>(p_kbkb, p_wq2b, p_K2f, QUERY, QIN);
    k2quant_kernel<<<NKB, 256>>>();
    recurrent_kernel<<<NB, NT, SMEM_REC>>>(bq1, bih, bhh);
    wmma_gemm_kernel<<<dim3(NTOK / 128, SEQ / 128), 256>>>(p_decbf, p_wdecb, out, DECIN, NTOK);
    logsoftmax_kernel<<<SEQ, 512>>>(out, bdec);
}